// round 1
// baseline (speedup 1.0000x reference)
#include <cuda_runtime.h>
#include <math.h>

#define BB   4
#define NN   4096
#define DM   1024
#define HH   16
#define DHD  64
#define MMF  256
#define DFF  4096
#define BN   (BB*NN)      // 16384
#define BH   (BB*HH)      // 64

// ---------------- scratch (no allocations allowed) ----------------
__device__ float    g_q[(size_t)BN*DM];
__device__ float    g_k[(size_t)BN*DM];
__device__ float    g_v[(size_t)BN*DM];
__device__ float    g_qp[(size_t)BH*NN*MMF];
__device__ float    g_kp[(size_t)BH*NN*MMF];
__device__ float    g_diag_q[(size_t)BH*NN];
__device__ float    g_diag_k[(size_t)BH*NN];
__device__ unsigned g_kmax_enc[BH];
__device__ float    g_ksum_part[BH*16*MMF];
__device__ float    g_ksum[BH*MMF];
__device__ float    g_ctx[(size_t)BH*MMF*DHD];
__device__ float    g_denom[(size_t)BH*NN];
__device__ float    g_attn_in[(size_t)BN*DM];
__device__ float    g_attn[(size_t)BN*DM];
__device__ float    g_x[(size_t)BN*DM];
__device__ float    g_h1[(size_t)BN*DFF];
__device__ float    g_ff[(size_t)BN*DM];

// ---------------- helpers ----------------
__device__ __forceinline__ unsigned encf(float f) {
    unsigned u = __float_as_uint(f);
    return (u & 0x80000000u) ? ~u : (u | 0x80000000u);
}
__device__ __forceinline__ float decf(unsigned e) {
    return __uint_as_float((e & 0x80000000u) ? (e ^ 0x80000000u) : ~e);
}

// ---------------- generic SGEMM: C[M,N] = A[M,K] @ B[N,K]^T + bias, opt ReLU ----------------
// 128x128 tile, BK=8, 256 threads, 8x8 per-thread micro-tile.
template<int RELU>
__global__ void __launch_bounds__(256) sgemm_bt(
    const float* __restrict__ A, const float* __restrict__ B,
    const float* __restrict__ bias, float* __restrict__ C,
    int Mr, int Nc, int K)
{
    __shared__ float As[8][132];
    __shared__ float Bs[8][132];
    int tid  = threadIdx.x;
    int row0 = blockIdx.y * 128, col0 = blockIdx.x * 128;
    int lr = tid >> 1;
    int lc = (tid & 1) * 4;
    const float* Ap = A + (size_t)(row0 + lr) * K + lc;
    const float* Bp = B + (size_t)(col0 + lr) * K + lc;
    int tx = tid & 15, ty = tid >> 4;

    float acc[8][8];
#pragma unroll
    for (int i = 0; i < 8; i++)
#pragma unroll
        for (int j = 0; j < 8; j++) acc[i][j] = 0.f;

    for (int k0 = 0; k0 < K; k0 += 8) {
        float4 av = *(const float4*)(Ap + k0);
        float4 bv = *(const float4*)(Bp + k0);
        __syncthreads();
        As[lc + 0][lr] = av.x; As[lc + 1][lr] = av.y;
        As[lc + 2][lr] = av.z; As[lc + 3][lr] = av.w;
        Bs[lc + 0][lr] = bv.x; Bs[lc + 1][lr] = bv.y;
        Bs[lc + 2][lr] = bv.z; Bs[lc + 3][lr] = bv.w;
        __syncthreads();
#pragma unroll
        for (int kk = 0; kk < 8; kk++) {
            float4 a0 = *(const float4*)&As[kk][ty * 8];
            float4 a1 = *(const float4*)&As[kk][ty * 8 + 4];
            float4 b0 = *(const float4*)&Bs[kk][tx * 8];
            float4 b1 = *(const float4*)&Bs[kk][tx * 8 + 4];
            float ar[8] = {a0.x,a0.y,a0.z,a0.w,a1.x,a1.y,a1.z,a1.w};
            float br[8] = {b0.x,b0.y,b0.z,b0.w,b1.x,b1.y,b1.z,b1.w};
#pragma unroll
            for (int i = 0; i < 8; i++)
#pragma unroll
                for (int j = 0; j < 8; j++)
                    acc[i][j] += ar[i] * br[j];
        }
    }

#pragma unroll
    for (int i = 0; i < 8; i++) {
        int r  = row0 + ty * 8 + i;
        int c0 = col0 + tx * 8;
        float4 o0, o1;
        o0.x = acc[i][0] + bias[c0 + 0];
        o0.y = acc[i][1] + bias[c0 + 1];
        o0.z = acc[i][2] + bias[c0 + 2];
        o0.w = acc[i][3] + bias[c0 + 3];
        o1.x = acc[i][4] + bias[c0 + 4];
        o1.y = acc[i][5] + bias[c0 + 5];
        o1.z = acc[i][6] + bias[c0 + 6];
        o1.w = acc[i][7] + bias[c0 + 7];
        if (RELU) {
            o0.x = fmaxf(o0.x, 0.f); o0.y = fmaxf(o0.y, 0.f);
            o0.z = fmaxf(o0.z, 0.f); o0.w = fmaxf(o0.w, 0.f);
            o1.x = fmaxf(o1.x, 0.f); o1.y = fmaxf(o1.y, 0.f);
            o1.z = fmaxf(o1.z, 0.f); o1.w = fmaxf(o1.w, 0.f);
        }
        *(float4*)(C + (size_t)r * Nc + c0)     = o0;
        *(float4*)(C + (size_t)r * Nc + c0 + 4) = o1;
    }
}

// ---------------- xp = norm * (X_head @ proj^T) ----------------
// X layout [b,n,h,d] flattened as [BN, DM]; out layout [(bh)*NN + n, m]
// grid.x = BH*4 (bh, m-tile of 64), grid.y = NN/64, 256 threads, 4x4 micro.
__global__ void __launch_bounds__(256) feat_xp(
    const float* __restrict__ X, const float* __restrict__ proj,
    float* __restrict__ out)
{
    __shared__ float xs[64][65];  // [d][n]
    __shared__ float ps[64][65];  // [d][m]
    int bh = blockIdx.x >> 2;
    int m0 = (blockIdx.x & 3) * 64;
    int b = bh >> 4, h = bh & 15;
    int n0 = blockIdx.y * 64;
    int tid = threadIdx.x;
#pragma unroll
    for (int c = 0; c < 16; c++) {
        int flat = c * 256 + tid;
        int r = flat >> 6, d = flat & 63;
        xs[d][r] = X[(size_t)(b * NN + n0 + r) * DM + h * DHD + d];
        ps[d][r] = proj[(m0 + r) * DHD + d];
    }
    __syncthreads();
    int tx = tid & 15, ty = tid >> 4;
    float acc[4][4] = {};
#pragma unroll
    for (int d = 0; d < 64; d++) {
        float a[4], p[4];
#pragma unroll
        for (int i = 0; i < 4; i++) a[i] = xs[d][ty * 4 + i];
#pragma unroll
        for (int j = 0; j < 4; j++) p[j] = ps[d][tx * 4 + j];
#pragma unroll
        for (int i = 0; i < 4; i++)
#pragma unroll
            for (int j = 0; j < 4; j++) acc[i][j] += a[i] * p[j];
    }
    const float NORM = 0.35355339059327373f;  // 64^-0.25
#pragma unroll
    for (int i = 0; i < 4; i++) {
        size_t ro = ((size_t)bh * NN + n0 + ty * 4 + i) * MMF + m0;
#pragma unroll
        for (int j = 0; j < 4; j++) out[ro + tx * 4 + j] = acc[i][j] * NORM;
    }
}

// ---------------- diag = 0.5*norm^2*sum_d x^2 = sum_d x^2 / 16 ----------------
// one warp per (bh, n)
__global__ void __launch_bounds__(256) diag_kernel(
    const float* __restrict__ X, float* __restrict__ diag)
{
    int gw   = blockIdx.x * 8 + (threadIdx.x >> 5);
    int lane = threadIdx.x & 31;
    int bh = gw >> 12;      // / NN
    int n  = gw & 4095;
    int b = bh >> 4, h = bh & 15;
    const float* p = X + (size_t)(b * NN + n) * DM + h * DHD;
    float x0 = p[lane], x1 = p[lane + 32];
    float s = x0 * x0 + x1 * x1;
#pragma unroll
    for (int o = 16; o > 0; o >>= 1) s += __shfl_xor_sync(0xffffffffu, s, o);
    if (lane == 0) diag[gw] = s * 0.0625f;
}

// ---------------- Q: per-row stab + exp, in place ----------------
__global__ void __launch_bounds__(256) q_exp(
    float* __restrict__ qp, const float* __restrict__ diag)
{
    int row = blockIdx.x;
    float* p = qp + (size_t)row * MMF;
    int tid = threadIdx.x;
    float v = p[tid];
    float mx = v;
#pragma unroll
    for (int o = 16; o > 0; o >>= 1) mx = fmaxf(mx, __shfl_xor_sync(0xffffffffu, mx, o));
    __shared__ float red[8];
    if ((tid & 31) == 0) red[tid >> 5] = mx;
    __syncthreads();
    float stab = red[0];
#pragma unroll
    for (int i = 1; i < 8; i++) stab = fmaxf(stab, red[i]);
    float d = diag[row];
    p[tid] = 0.0625f * (expf(v - d - stab) + 1e-4f);
}

__global__ void init_kmax(unsigned* kmax)
{
    if (threadIdx.x < BH) kmax[threadIdx.x] = 0u;
}

// ---------------- K: global per-head max (deterministic atomicMax on encoded uint) ----------------
__global__ void __launch_bounds__(256) k_max(
    const float* __restrict__ kp, unsigned* __restrict__ kmax)
{
    int bh = blockIdx.x, ch = blockIdx.y;  // 32 chunks of 128 rows
    const float* base = kp + ((size_t)bh * NN + ch * 128) * MMF;
    float mx = -3.0e38f;
    for (int i = threadIdx.x; i < 128 * MMF; i += 256) mx = fmaxf(mx, base[i]);
#pragma unroll
    for (int o = 16; o > 0; o >>= 1) mx = fmaxf(mx, __shfl_xor_sync(0xffffffffu, mx, o));
    __shared__ float red[8];
    if ((threadIdx.x & 31) == 0) red[threadIdx.x >> 5] = mx;
    __syncthreads();
    if (threadIdx.x == 0) {
        float bm = red[0];
#pragma unroll
        for (int i = 1; i < 8; i++) bm = fmaxf(bm, red[i]);
        atomicMax(&kmax[bh], encf(bm));
    }
}

__global__ void __launch_bounds__(256) k_exp(
    float* __restrict__ kp, const float* __restrict__ diag,
    const unsigned* __restrict__ kmax)
{
    size_t idx = (size_t)blockIdx.x * 256 + threadIdx.x;
    int row = (int)(idx >> 8);   // / MMF
    int bh  = row >> 12;         // / NN
    float stab = decf(kmax[bh]);
    float v = kp[idx];
    kp[idx] = 0.0625f * (expf(v - diag[row] - stab) + 1e-4f);
}

// ---------------- k_sum over n (deterministic split + reduce) ----------------
__global__ void __launch_bounds__(256) ksum_part(
    const float* __restrict__ kp, float* __restrict__ part)
{
    int bh = blockIdx.x, ch = blockIdx.y;
    int m = threadIdx.x;
    float s = 0.f;
    const float* base = kp + ((size_t)bh * NN + ch * 256) * MMF + m;
    for (int n = 0; n < 256; n++) s += base[(size_t)n * MMF];
    part[(bh * 16 + ch) * MMF + m] = s;
}
__global__ void __launch_bounds__(256) ksum_final(
    const float* __restrict__ part, float* __restrict__ ksum)
{
    int bh = blockIdx.x, m = threadIdx.x;
    float s = 0.f;
#pragma unroll
    for (int c = 0; c < 16; c++) s += part[(bh * 16 + c) * MMF + m];
    ksum[bh * MMF + m] = s;
}

// ---------------- ctx[bh,m,d] = sum_n kp[bh,n,m] * v[b,n,h,d] ----------------
// grid.x = BH*4 (m-tile of 64), 256 threads, 4x4 micro, K=NN
__global__ void __launch_bounds__(256) ctx_kernel(
    const float* __restrict__ kp, const float* __restrict__ V,
    float* __restrict__ ctx)
{
    __shared__ float ks[32][65];  // [n][m]
    __shared__ float vs[32][65];  // [n][d]
    int bh = blockIdx.x >> 2;
    int m0 = (blockIdx.x & 3) * 64;
    int b = bh >> 4, h = bh & 15;
    int tid = threadIdx.x, tx = tid & 15, ty = tid >> 4;
    float acc[4][4] = {};
    for (int n0 = 0; n0 < NN; n0 += 32) {
#pragma unroll
        for (int c = 0; c < 8; c++) {
            int flat = c * 256 + tid;
            int r = flat >> 6, col = flat & 63;
            ks[r][col] = kp[((size_t)bh * NN + n0 + r) * MMF + m0 + col];
            vs[r][col] = V[(size_t)(b * NN + n0 + r) * DM + h * DHD + col];
        }
        __syncthreads();
#pragma unroll
        for (int nn = 0; nn < 32; nn++) {
            float a[4], bv[4];
#pragma unroll
            for (int i = 0; i < 4; i++) a[i] = ks[nn][ty * 4 + i];
#pragma unroll
            for (int j = 0; j < 4; j++) bv[j] = vs[nn][tx * 4 + j];
#pragma unroll
            for (int i = 0; i < 4; i++)
#pragma unroll
                for (int j = 0; j < 4; j++) acc[i][j] += a[i] * bv[j];
        }
        __syncthreads();
    }
#pragma unroll
    for (int i = 0; i < 4; i++)
#pragma unroll
        for (int j = 0; j < 4; j++)
            ctx[((size_t)bh * MMF + m0 + ty * 4 + i) * DHD + tx * 4 + j] = acc[i][j];
}

// ---------------- denom[bh,n] = sum_m qp[bh,n,m]*ksum[bh,m] ----------------
__global__ void __launch_bounds__(256) denom_kernel(
    const float* __restrict__ qp, const float* __restrict__ ksum,
    float* __restrict__ den)
{
    int gw   = blockIdx.x * 8 + (threadIdx.x >> 5);
    int lane = threadIdx.x & 31;
    int bh = gw >> 12;
    const float* p  = qp + (size_t)gw * MMF;
    const float* ks = ksum + bh * MMF;
    float s = 0.f;
#pragma unroll
    for (int m = 0; m < MMF; m += 32) s += p[m + lane] * ks[m + lane];
#pragma unroll
    for (int o = 16; o > 0; o >>= 1) s += __shfl_xor_sync(0xffffffffu, s, o);
    if (lane == 0) den[gw] = s;
}

// ---------------- out[b,n,h,d] = (qp @ ctx)/denom ----------------
// grid.x = bh, grid.y = NN/64, 256 threads, 4x4 micro, K=MMF=256
__global__ void __launch_bounds__(256) out_attn(
    const float* __restrict__ qp, const float* __restrict__ ctx,
    const float* __restrict__ den, float* __restrict__ out)
{
    __shared__ float qs[64][65];  // [m][n]
    __shared__ float cs[64][65];  // [m][d]
    int bh = blockIdx.x;
    int b = bh >> 4, h = bh & 15;
    int n0 = blockIdx.y * 64;
    int tid = threadIdx.x, tx = tid & 15, ty = tid >> 4;
    float acc[4][4] = {};
    for (int m0 = 0; m0 < MMF; m0 += 64) {
#pragma unroll
        for (int c = 0; c < 16; c++) {
            int flat = c * 256 + tid;
            int r = flat >> 6, col = flat & 63;
            qs[col][r] = qp[((size_t)bh * NN + n0 + r) * MMF + m0 + col];
            cs[r][col] = ctx[((size_t)bh * MMF + m0 + r) * DHD + col];
        }
        __syncthreads();
#pragma unroll
        for (int mm = 0; mm < 64; mm++) {
            float a[4], cv[4];
#pragma unroll
            for (int i = 0; i < 4; i++) a[i] = qs[mm][ty * 4 + i];
#pragma unroll
            for (int j = 0; j < 4; j++) cv[j] = cs[mm][tx * 4 + j];
#pragma unroll
            for (int i = 0; i < 4; i++)
#pragma unroll
                for (int j = 0; j < 4; j++) acc[i][j] += a[i] * cv[j];
        }
        __syncthreads();
    }
#pragma unroll
    for (int i = 0; i < 4; i++) {
        int n = n0 + ty * 4 + i;
        float inv = 1.f / den[(size_t)bh * NN + n];
#pragma unroll
        for (int j = 0; j < 4; j++)
            out[(size_t)(b * NN + n) * DM + h * DHD + tx * 4 + j] = acc[i][j] * inv;
    }
}

// ---------------- fused residual-add + LayerNorm ----------------
__global__ void __launch_bounds__(256) add_ln(
    const float* __restrict__ A, const float* __restrict__ Bt,
    const float* __restrict__ g, const float* __restrict__ be,
    float* __restrict__ out)
{
    int row = blockIdx.x;
    int tid = threadIdx.x;
    const float4* pa = (const float4*)(A + (size_t)row * DM);
    const float4* pb = (const float4*)(Bt + (size_t)row * DM);
    float4 xa = pa[tid], xb = pb[tid];
    float x0 = xa.x + xb.x, x1 = xa.y + xb.y, x2 = xa.z + xb.z, x3 = xa.w + xb.w;
    float s  = x0 + x1 + x2 + x3;
    float ss = x0 * x0 + x1 * x1 + x2 * x2 + x3 * x3;
#pragma unroll
    for (int o = 16; o > 0; o >>= 1) {
        s  += __shfl_xor_sync(0xffffffffu, s, o);
        ss += __shfl_xor_sync(0xffffffffu, ss, o);
    }
    __shared__ float rs[8], rss[8];
    if ((tid & 31) == 0) { rs[tid >> 5] = s; rss[tid >> 5] = ss; }
    __syncthreads();
    float S = 0.f, SS = 0.f;
#pragma unroll
    for (int i = 0; i < 8; i++) { S += rs[i]; SS += rss[i]; }
    float mu  = S * (1.f / DM);
    float var = SS * (1.f / DM) - mu * mu;
    var = fmaxf(var, 0.f);
    float rstd = rsqrtf(var + 1e-5f);
    float4 gv = ((const float4*)g)[tid];
    float4 bv = ((const float4*)be)[tid];
    float4 o;
    o.x = (x0 - mu) * rstd * gv.x + bv.x;
    o.y = (x1 - mu) * rstd * gv.y + bv.y;
    o.z = (x2 - mu) * rstd * gv.z + bv.z;
    o.w = (x3 - mu) * rstd * gv.w + bv.w;
    ((float4*)(out + (size_t)row * DM))[tid] = o;
}

// ---------------- launch ----------------
extern "C" void kernel_launch(void* const* d_in, const int* in_sizes, int n_in,
                              void* d_out, int out_size)
{
    const float* video = (const float*)d_in[0];
    const float* Wq = (const float*)d_in[1];  const float* bq = (const float*)d_in[2];
    const float* Wk = (const float*)d_in[3];  const float* bk = (const float*)d_in[4];
    const float* Wv = (const float*)d_in[5];  const float* bv = (const float*)d_in[6];
    const float* Wo = (const float*)d_in[7];  const float* bo = (const float*)d_in[8];
    const float* proj = (const float*)d_in[9];
    const float* W1 = (const float*)d_in[10]; const float* b1 = (const float*)d_in[11];
    const float* W2 = (const float*)d_in[12]; const float* b2 = (const float*)d_in[13];
    const float* g2 = (const float*)d_in[14]; const float* be2 = (const float*)d_in[15];
    const float* g3 = (const float*)d_in[16]; const float* be3 = (const float*)d_in[17];
    float* out = (float*)d_out;

    float *q, *k, *v, *qp, *kp, *dq, *dk, *ksp, *ks, *ctx, *den, *ain, *attn, *x, *h1, *ff;
    unsigned* kme;
    cudaGetSymbolAddress((void**)&q,   g_q);
    cudaGetSymbolAddress((void**)&k,   g_k);
    cudaGetSymbolAddress((void**)&v,   g_v);
    cudaGetSymbolAddress((void**)&qp,  g_qp);
    cudaGetSymbolAddress((void**)&kp,  g_kp);
    cudaGetSymbolAddress((void**)&dq,  g_diag_q);
    cudaGetSymbolAddress((void**)&dk,  g_diag_k);
    cudaGetSymbolAddress((void**)&kme, g_kmax_enc);
    cudaGetSymbolAddress((void**)&ksp, g_ksum_part);
    cudaGetSymbolAddress((void**)&ks,  g_ksum);
    cudaGetSymbolAddress((void**)&ctx, g_ctx);
    cudaGetSymbolAddress((void**)&den, g_denom);
    cudaGetSymbolAddress((void**)&ain, g_attn_in);
    cudaGetSymbolAddress((void**)&attn,g_attn);
    cudaGetSymbolAddress((void**)&x,   g_x);
    cudaGetSymbolAddress((void**)&h1,  g_h1);
    cudaGetSymbolAddress((void**)&ff,  g_ff);

    dim3 gD(DM / 128, BN / 128);     // (8, 128)
    sgemm_bt<0><<<gD, 256>>>(video, Wq, bq, q, BN, DM, DM);
    sgemm_bt<0><<<gD, 256>>>(video, Wk, bk, k, BN, DM, DM);
    sgemm_bt<0><<<gD, 256>>>(video, Wv, bv, v, BN, DM, DM);

    dim3 gF(BH * 4, NN / 64);
    feat_xp<<<gF, 256>>>(q, proj, qp);
    feat_xp<<<gF, 256>>>(k, proj, kp);
    diag_kernel<<<BH * NN / 8, 256>>>(q, dq);
    diag_kernel<<<BH * NN / 8, 256>>>(k, dk);

    q_exp<<<BH * NN, 256>>>(qp, dq);

    init_kmax<<<1, 64>>>(kme);
    k_max<<<dim3(BH, 32), 256>>>(kp, kme);
    k_exp<<<(BH * NN * MMF) / 256, 256>>>(kp, dk, kme);

    ksum_part<<<dim3(BH, 16), 256>>>(kp, ksp);
    ksum_final<<<BH, 256>>>(ksp, ks);
    ctx_kernel<<<BH * 4, 256>>>(kp, v, ctx);
    denom_kernel<<<BH * NN / 8, 256>>>(qp, ks, den);
    out_attn<<<dim3(BH, NN / 64), 256>>>(qp, ctx, den, ain);

    sgemm_bt<0><<<gD, 256>>>(ain, Wo, bo, attn, BN, DM, DM);
    add_ln<<<BN, 256>>>(video, attn, g2, be2, x);
    sgemm_bt<1><<<dim3(DFF / 128, BN / 128), 256>>>(x, W1, b1, h1, BN, DFF, DM);
    sgemm_bt<0><<<gD, 256>>>(h1, W2, b2, ff, BN, DM, DFF);
    add_ln<<<BN, 256>>>(x, ff, g3, be3, out);
}

// round 3
// speedup vs baseline: 2.1750x; 2.1750x over previous
#include <cuda_runtime.h>
#include <math.h>

#define BB   4
#define NN   4096
#define DM   1024
#define HH   16
#define DHD  64
#define MMF  256
#define DFF  4096
#define BN   (BB*NN)      // 16384
#define BH   (BB*HH)      // 64

// ---------------- scratch (no allocations allowed) ----------------
__device__ float    g_q[(size_t)BN*DM];
__device__ float    g_k[(size_t)BN*DM];
__device__ float    g_v[(size_t)BN*DM];
__device__ float    g_qp[(size_t)BH*NN*MMF];
__device__ float    g_kp[(size_t)BH*NN*MMF];
__device__ float    g_diag_q[(size_t)BH*NN];
__device__ float    g_diag_k[(size_t)BH*NN];
__device__ unsigned g_kmax_enc[BH];
__device__ float    g_ksum_part[BH*16*MMF];
__device__ float    g_ksum[BH*MMF];
__device__ float    g_ctx[(size_t)BH*MMF*DHD];
__device__ float    g_denom[(size_t)BH*NN];
__device__ float    g_attn_in[(size_t)BN*DM];
__device__ float    g_attn[(size_t)BN*DM];
__device__ float    g_x[(size_t)BN*DM];
__device__ float    g_h1[(size_t)BN*DFF];
__device__ float    g_ff[(size_t)BN*DM];

// ---------------- helpers ----------------
__device__ __forceinline__ unsigned encf(float f) {
    unsigned u = __float_as_uint(f);
    return (u & 0x80000000u) ? ~u : (u | 0x80000000u);
}
__device__ __forceinline__ float decf(unsigned e) {
    return __uint_as_float((e & 0x80000000u) ? (e ^ 0x80000000u) : ~e);
}
__device__ __forceinline__ unsigned f2tf32(float f) {
    unsigned r;
    asm("cvt.rna.tf32.f32 %0, %1;" : "=r"(r) : "f"(f));
    return r;
}
__device__ __forceinline__ void mma_tf32(
    float c[4], const unsigned a[4], const unsigned b[2])
{
    asm volatile(
        "mma.sync.aligned.m16n8k8.row.col.f32.tf32.tf32.f32 "
        "{%0,%1,%2,%3}, {%4,%5,%6,%7}, {%8,%9}, {%0,%1,%2,%3};"
        : "+f"(c[0]), "+f"(c[1]), "+f"(c[2]), "+f"(c[3])
        : "r"(a[0]), "r"(a[1]), "r"(a[2]), "r"(a[3]),
          "r"(b[0]), "r"(b[1]));
}

// ---------------- tf32 tensor-core GEMM: C[M,N] = A[M,K] @ B[N,K]^T + bias, opt ReLU ----------------
// 128x128 block tile, BK=32, 256 threads (8 warps, each 64x32 warp tile).
// smem stride 36 floats => fragment LDS are bank-conflict-free.
template<int RELU>
__global__ void __launch_bounds__(256) gemm_tf32(
    const float* __restrict__ A, const float* __restrict__ B,
    const float* __restrict__ bias, float* __restrict__ C,
    int Mr, int Nc, int K)
{
    __shared__ unsigned As[128 * 36];
    __shared__ unsigned Bs[128 * 36];

    int tid  = threadIdx.x;
    int wid  = tid >> 5, lane = tid & 31;
    int wm   = (wid >> 2) * 64;      // warp m offset (0 or 64)
    int wn   = (wid & 3) * 32;       // warp n offset (0,32,64,96)
    int g    = lane >> 2;            // group id 0..7
    int tg   = lane & 3;             // thread-in-group 0..3
    int row0 = blockIdx.y * 128, col0 = blockIdx.x * 128;

    int lr = tid >> 3;               // 0..31 (load row within 32-row wave)
    int lc = (tid & 7) * 4;          // 0..28 (k column, float4)
    const float* Ap = A + (size_t)(row0 + lr) * K + lc;
    const float* Bp = B + (size_t)(col0 + lr) * K + lc;

    float acc[4][4][4];
#pragma unroll
    for (int i = 0; i < 4; i++)
#pragma unroll
        for (int j = 0; j < 4; j++)
#pragma unroll
            for (int r = 0; r < 4; r++) acc[i][j][r] = 0.f;

    for (int k0 = 0; k0 < K; k0 += 32) {
        float4 av[4], bv[4];
#pragma unroll
        for (int r = 0; r < 4; r++) {
            av[r] = *(const float4*)(Ap + (size_t)(r * 32) * K + k0);
            bv[r] = *(const float4*)(Bp + (size_t)(r * 32) * K + k0);
        }
        __syncthreads();
#pragma unroll
        for (int r = 0; r < 4; r++) {
            unsigned* pa = &As[(lr + r * 32) * 36 + lc];
            pa[0] = f2tf32(av[r].x); pa[1] = f2tf32(av[r].y);
            pa[2] = f2tf32(av[r].z); pa[3] = f2tf32(av[r].w);
            unsigned* pb = &Bs[(lr + r * 32) * 36 + lc];
            pb[0] = f2tf32(bv[r].x); pb[1] = f2tf32(bv[r].y);
            pb[2] = f2tf32(bv[r].z); pb[3] = f2tf32(bv[r].w);
        }
        __syncthreads();
#pragma unroll
        for (int kk = 0; kk < 4; kk++) {
            int kb = kk * 8;
            unsigned afr[4][4], bfr[4][2];
#pragma unroll
            for (int i = 0; i < 4; i++) {
                int r = wm + i * 16 + g;
                afr[i][0] = As[r * 36 + kb + tg];
                afr[i][1] = As[(r + 8) * 36 + kb + tg];
                afr[i][2] = As[r * 36 + kb + tg + 4];
                afr[i][3] = As[(r + 8) * 36 + kb + tg + 4];
            }
#pragma unroll
            for (int j = 0; j < 4; j++) {
                int c = wn + j * 8 + g;
                bfr[j][0] = Bs[c * 36 + kb + tg];
                bfr[j][1] = Bs[c * 36 + kb + tg + 4];
            }
#pragma unroll
            for (int i = 0; i < 4; i++)
#pragma unroll
                for (int j = 0; j < 4; j++)
                    mma_tf32(acc[i][j], afr[i], bfr[j]);
        }
    }

#pragma unroll
    for (int i = 0; i < 4; i++) {
        int rt = row0 + wm + i * 16 + g;
#pragma unroll
        for (int j = 0; j < 4; j++) {
            int c = col0 + wn + j * 8 + 2 * tg;
            float b0v = bias[c], b1v = bias[c + 1];
            float2 t0, t1;
            t0.x = acc[i][j][0] + b0v; t0.y = acc[i][j][1] + b1v;
            t1.x = acc[i][j][2] + b0v; t1.y = acc[i][j][3] + b1v;
            if (RELU) {
                t0.x = fmaxf(t0.x, 0.f); t0.y = fmaxf(t0.y, 0.f);
                t1.x = fmaxf(t1.x, 0.f); t1.y = fmaxf(t1.y, 0.f);
            }
            *(float2*)(C + (size_t)rt * Nc + c)       = t0;
            *(float2*)(C + (size_t)(rt + 8) * Nc + c) = t1;
        }
    }
}

// ---------------- xp = norm * (X_head @ proj^T) ----------------
__global__ void __launch_bounds__(256) feat_xp(
    const float* __restrict__ X, const float* __restrict__ proj,
    float* __restrict__ out)
{
    __shared__ float xs[64][65];  // [d][n]
    __shared__ float ps[64][65];  // [d][m]
    int bh = blockIdx.x >> 2;
    int m0 = (blockIdx.x & 3) * 64;
    int b = bh >> 4, h = bh & 15;
    int n0 = blockIdx.y * 64;
    int tid = threadIdx.x;
#pragma unroll
    for (int c = 0; c < 16; c++) {
        int flat = c * 256 + tid;
        int r = flat >> 6, d = flat & 63;
        xs[d][r] = X[(size_t)(b * NN + n0 + r) * DM + h * DHD + d];
        ps[d][r] = proj[(m0 + r) * DHD + d];
    }
    __syncthreads();
    int tx = tid & 15, ty = tid >> 4;
    float acc[4][4] = {};
#pragma unroll
    for (int d = 0; d < 64; d++) {
        float a[4], p[4];
#pragma unroll
        for (int i = 0; i < 4; i++) a[i] = xs[d][ty * 4 + i];
#pragma unroll
        for (int j = 0; j < 4; j++) p[j] = ps[d][tx * 4 + j];
#pragma unroll
        for (int i = 0; i < 4; i++)
#pragma unroll
            for (int j = 0; j < 4; j++) acc[i][j] += a[i] * p[j];
    }
    const float NORM = 0.35355339059327373f;  // 64^-0.25
#pragma unroll
    for (int i = 0; i < 4; i++) {
        size_t ro = ((size_t)bh * NN + n0 + ty * 4 + i) * MMF + m0;
#pragma unroll
        for (int j = 0; j < 4; j++) out[ro + tx * 4 + j] = acc[i][j] * NORM;
    }
}

// ---------------- diag = 0.5*norm^2*sum_d x^2 = sum_d x^2 / 16 ----------------
__global__ void __launch_bounds__(256) diag_kernel(
    const float* __restrict__ X, float* __restrict__ diag)
{
    int gw   = blockIdx.x * 8 + (threadIdx.x >> 5);
    int lane = threadIdx.x & 31;
    int bh = gw >> 12;      // / NN
    int n  = gw & 4095;
    int b = bh >> 4, h = bh & 15;
    const float* p = X + (size_t)(b * NN + n) * DM + h * DHD;
    float x0 = p[lane], x1 = p[lane + 32];
    float s = x0 * x0 + x1 * x1;
#pragma unroll
    for (int o = 16; o > 0; o >>= 1) s += __shfl_xor_sync(0xffffffffu, s, o);
    if (lane == 0) diag[gw] = s * 0.0625f;
}

// ---------------- Q: per-row stab + exp, in place ----------------
__global__ void __launch_bounds__(256) q_exp(
    float* __restrict__ qp, const float* __restrict__ diag)
{
    int row = blockIdx.x;
    float* p = qp + (size_t)row * MMF;
    int tid = threadIdx.x;
    float v = p[tid];
    float mx = v;
#pragma unroll
    for (int o = 16; o > 0; o >>= 1) mx = fmaxf(mx, __shfl_xor_sync(0xffffffffu, mx, o));
    __shared__ float red[8];
    if ((tid & 31) == 0) red[tid >> 5] = mx;
    __syncthreads();
    float stab = red[0];
#pragma unroll
    for (int i = 1; i < 8; i++) stab = fmaxf(stab, red[i]);
    float d = diag[row];
    p[tid] = 0.0625f * (expf(v - d - stab) + 1e-4f);
}

__global__ void init_kmax(unsigned* kmax)
{
    if (threadIdx.x < BH) kmax[threadIdx.x] = 0u;
}

// ---------------- K: global per-head max ----------------
__global__ void __launch_bounds__(256) k_max(
    const float* __restrict__ kp, unsigned* __restrict__ kmax)
{
    int bh = blockIdx.x, ch = blockIdx.y;
    const float* base = kp + ((size_t)bh * NN + ch * 128) * MMF;
    float mx = -3.0e38f;
    for (int i = threadIdx.x; i < 128 * MMF; i += 256) mx = fmaxf(mx, base[i]);
#pragma unroll
    for (int o = 16; o > 0; o >>= 1) mx = fmaxf(mx, __shfl_xor_sync(0xffffffffu, mx, o));
    __shared__ float red[8];
    if ((threadIdx.x & 31) == 0) red[threadIdx.x >> 5] = mx;
    __syncthreads();
    if (threadIdx.x == 0) {
        float bm = red[0];
#pragma unroll
        for (int i = 1; i < 8; i++) bm = fmaxf(bm, red[i]);
        atomicMax(&kmax[bh], encf(bm));
    }
}

__global__ void __launch_bounds__(256) k_exp(
    float* __restrict__ kp, const float* __restrict__ diag,
    const unsigned* __restrict__ kmax)
{
    size_t idx = (size_t)blockIdx.x * 256 + threadIdx.x;
    int row = (int)(idx >> 8);
    int bh  = row >> 12;
    float stab = decf(kmax[bh]);
    float v = kp[idx];
    kp[idx] = 0.0625f * (expf(v - diag[row] - stab) + 1e-4f);
}

// ---------------- k_sum over n ----------------
__global__ void __launch_bounds__(256) ksum_part(
    const float* __restrict__ kp, float* __restrict__ part)
{
    int bh = blockIdx.x, ch = blockIdx.y;
    int m = threadIdx.x;
    float s = 0.f;
    const float* base = kp + ((size_t)bh * NN + ch * 256) * MMF + m;
    for (int n = 0; n < 256; n++) s += base[(size_t)n * MMF];
    part[(bh * 16 + ch) * MMF + m] = s;
}
__global__ void __launch_bounds__(256) ksum_final(
    const float* __restrict__ part, float* __restrict__ ksum)
{
    int bh = blockIdx.x, m = threadIdx.x;
    float s = 0.f;
#pragma unroll
    for (int c = 0; c < 16; c++) s += part[(bh * 16 + c) * MMF + m];
    ksum[bh * MMF + m] = s;
}

// ---------------- ctx[bh,m,d] = sum_n kp[bh,n,m] * v[b,n,h,d] ----------------
__global__ void __launch_bounds__(256) ctx_kernel(
    const float* __restrict__ kp, const float* __restrict__ V,
    float* __restrict__ ctx)
{
    __shared__ float ks[32][65];
    __shared__ float vs[32][65];
    int bh = blockIdx.x >> 2;
    int m0 = (blockIdx.x & 3) * 64;
    int b = bh >> 4, h = bh & 15;
    int tid = threadIdx.x, tx = tid & 15, ty = tid >> 4;
    float acc[4][4] = {};
    for (int n0 = 0; n0 < NN; n0 += 32) {
#pragma unroll
        for (int c = 0; c < 8; c++) {
            int flat = c * 256 + tid;
            int r = flat >> 6, col = flat & 63;
            ks[r][col] = kp[((size_t)bh * NN + n0 + r) * MMF + m0 + col];
            vs[r][col] = V[(size_t)(b * NN + n0 + r) * DM + h * DHD + col];
        }
        __syncthreads();
#pragma unroll
        for (int nn = 0; nn < 32; nn++) {
            float a[4], bv[4];
#pragma unroll
            for (int i = 0; i < 4; i++) a[i] = ks[nn][ty * 4 + i];
#pragma unroll
            for (int j = 0; j < 4; j++) bv[j] = vs[nn][tx * 4 + j];
#pragma unroll
            for (int i = 0; i < 4; i++)
#pragma unroll
                for (int j = 0; j < 4; j++) acc[i][j] += a[i] * bv[j];
        }
        __syncthreads();
    }
#pragma unroll
    for (int i = 0; i < 4; i++)
#pragma unroll
        for (int j = 0; j < 4; j++)
            ctx[((size_t)bh * MMF + m0 + ty * 4 + i) * DHD + tx * 4 + j] = acc[i][j];
}

// ---------------- denom[bh,n] = sum_m qp[bh,n,m]*ksum[bh,m] ----------------
__global__ void __launch_bounds__(256) denom_kernel(
    const float* __restrict__ qp, const float* __restrict__ ksum,
    float* __restrict__ den)
{
    int gw   = blockIdx.x * 8 + (threadIdx.x >> 5);
    int lane = threadIdx.x & 31;
    int bh = gw >> 12;
    const float* p  = qp + (size_t)gw * MMF;
    const float* ks = ksum + bh * MMF;
    float s = 0.f;
#pragma unroll
    for (int m = 0; m < MMF; m += 32) s += p[m + lane] * ks[m + lane];
#pragma unroll
    for (int o = 16; o > 0; o >>= 1) s += __shfl_xor_sync(0xffffffffu, s, o);
    if (lane == 0) den[gw] = s;
}

// ---------------- out[b,n,h,d] = (qp @ ctx)/denom ----------------
__global__ void __launch_bounds__(256) out_attn(
    const float* __restrict__ qp, const float* __restrict__ ctx,
    const float* __restrict__ den, float* __restrict__ out)
{
    __shared__ float qs[64][65];
    __shared__ float cs[64][65];
    int bh = blockIdx.x;
    int b = bh >> 4, h = bh & 15;
    int n0 = blockIdx.y * 64;
    int tid = threadIdx.x, tx = tid & 15, ty = tid >> 4;
    float acc[4][4] = {};
    for (int m0 = 0; m0 < MMF; m0 += 64) {
#pragma unroll
        for (int c = 0; c < 16; c++) {
            int flat = c * 256 + tid;
            int r = flat >> 6, col = flat & 63;
            qs[col][r] = qp[((size_t)bh * NN + n0 + r) * MMF + m0 + col];
            cs[r][col] = ctx[((size_t)bh * MMF + m0 + r) * DHD + col];
        }
        __syncthreads();
#pragma unroll
        for (int mm = 0; mm < 64; mm++) {
            float a[4], cv[4];
#pragma unroll
            for (int i = 0; i < 4; i++) a[i] = qs[mm][ty * 4 + i];
#pragma unroll
            for (int j = 0; j < 4; j++) cv[j] = cs[mm][tx * 4 + j];
#pragma unroll
            for (int i = 0; i < 4; i++)
#pragma unroll
                for (int j = 0; j < 4; j++) acc[i][j] += a[i] * cv[j];
        }
        __syncthreads();
    }
#pragma unroll
    for (int i = 0; i < 4; i++) {
        int n = n0 + ty * 4 + i;
        float inv = 1.f / den[(size_t)bh * NN + n];
#pragma unroll
        for (int j = 0; j < 4; j++)
            out[(size_t)(b * NN + n) * DM + h * DHD + tx * 4 + j] = acc[i][j] * inv;
    }
}

// ---------------- fused residual-add + LayerNorm ----------------
__global__ void __launch_bounds__(256) add_ln(
    const float* __restrict__ A, const float* __restrict__ Bt,
    const float* __restrict__ g, const float* __restrict__ be,
    float* __restrict__ out)
{
    int row = blockIdx.x;
    int tid = threadIdx.x;
    const float4* pa = (const float4*)(A + (size_t)row * DM);
    const float4* pb = (const float4*)(Bt + (size_t)row * DM);
    float4 xa = pa[tid], xb = pb[tid];
    float x0 = xa.x + xb.x, x1 = xa.y + xb.y, x2 = xa.z + xb.z, x3 = xa.w + xb.w;
    float s  = x0 + x1 + x2 + x3;
    float ss = x0 * x0 + x1 * x1 + x2 * x2 + x3 * x3;
#pragma unroll
    for (int o = 16; o > 0; o >>= 1) {
        s  += __shfl_xor_sync(0xffffffffu, s, o);
        ss += __shfl_xor_sync(0xffffffffu, ss, o);
    }
    __shared__ float rs[8], rss[8];
    if ((tid & 31) == 0) { rs[tid >> 5] = s; rss[tid >> 5] = ss; }
    __syncthreads();
    float S = 0.f, SS = 0.f;
#pragma unroll
    for (int i = 0; i < 8; i++) { S += rs[i]; SS += rss[i]; }
    float mu  = S * (1.f / DM);
    float var = SS * (1.f / DM) - mu * mu;
    var = fmaxf(var, 0.f);
    float rstd = rsqrtf(var + 1e-5f);
    float4 gv = ((const float4*)g)[tid];
    float4 bv = ((const float4*)be)[tid];
    float4 o;
    o.x = (x0 - mu) * rstd * gv.x + bv.x;
    o.y = (x1 - mu) * rstd * gv.y + bv.y;
    o.z = (x2 - mu) * rstd * gv.z + bv.z;
    o.w = (x3 - mu) * rstd * gv.w + bv.w;
    ((float4*)(out + (size_t)row * DM))[tid] = o;
}

// ---------------- launch ----------------
extern "C" void kernel_launch(void* const* d_in, const int* in_sizes, int n_in,
                              void* d_out, int out_size)
{
    const float* video = (const float*)d_in[0];
    const float* Wq = (const float*)d_in[1];  const float* bq = (const float*)d_in[2];
    const float* Wk = (const float*)d_in[3];  const float* bk = (const float*)d_in[4];
    const float* Wv = (const float*)d_in[5];  const float* bv = (const float*)d_in[6];
    const float* Wo = (const float*)d_in[7];  const float* bo = (const float*)d_in[8];
    const float* proj = (const float*)d_in[9];
    const float* W1 = (const float*)d_in[10]; const float* b1 = (const float*)d_in[11];
    const float* W2 = (const float*)d_in[12]; const float* b2 = (const float*)d_in[13];
    const float* g2 = (const float*)d_in[14]; const float* be2 = (const float*)d_in[15];
    const float* g3 = (const float*)d_in[16]; const float* be3 = (const float*)d_in[17];
    float* out = (float*)d_out;

    float *q, *k, *v, *qp, *kp, *dq, *dk, *ksp, *ks, *ctx, *den, *ain, *attn, *x, *h1, *ff;
    unsigned* kme;
    cudaGetSymbolAddress((void**)&q,   g_q);
    cudaGetSymbolAddress((void**)&k,   g_k);
    cudaGetSymbolAddress((void**)&v,   g_v);
    cudaGetSymbolAddress((void**)&qp,  g_qp);
    cudaGetSymbolAddress((void**)&kp,  g_kp);
    cudaGetSymbolAddress((void**)&dq,  g_diag_q);
    cudaGetSymbolAddress((void**)&dk,  g_diag_k);
    cudaGetSymbolAddress((void**)&kme, g_kmax_enc);
    cudaGetSymbolAddress((void**)&ksp, g_ksum_part);
    cudaGetSymbolAddress((void**)&ks,  g_ksum);
    cudaGetSymbolAddress((void**)&ctx, g_ctx);
    cudaGetSymbolAddress((void**)&den, g_denom);
    cudaGetSymbolAddress((void**)&ain, g_attn_in);
    cudaGetSymbolAddress((void**)&attn,g_attn);
    cudaGetSymbolAddress((void**)&x,   g_x);
    cudaGetSymbolAddress((void**)&h1,  g_h1);
    cudaGetSymbolAddress((void**)&ff,  g_ff);

    dim3 gD(DM / 128, BN / 128);     // (8, 128)
    gemm_tf32<0><<<gD, 256>>>(video, Wq, bq, q, BN, DM, DM);
    gemm_tf32<0><<<gD, 256>>>(video, Wk, bk, k, BN, DM, DM);
    gemm_tf32<0><<<gD, 256>>>(video, Wv, bv, v, BN, DM, DM);

    dim3 gF(BH * 4, NN / 64);
    feat_xp<<<gF, 256>>>(q, proj, qp);
    feat_xp<<<gF, 256>>>(k, proj, kp);
    diag_kernel<<<BH * NN / 8, 256>>>(q, dq);
    diag_kernel<<<BH * NN / 8, 256>>>(k, dk);

    q_exp<<<BH * NN, 256>>>(qp, dq);

    init_kmax<<<1, 64>>>(kme);
    k_max<<<dim3(BH, 32), 256>>>(kp, kme);
    k_exp<<<(BH * NN * MMF) / 256, 256>>>(kp, dk, kme);

    ksum_part<<<dim3(BH, 16), 256>>>(kp, ksp);
    ksum_final<<<BH, 256>>>(ksp, ks);
    ctx_kernel<<<BH * 4, 256>>>(kp, v, ctx);
    denom_kernel<<<BH * NN / 8, 256>>>(qp, ks, den);
    out_attn<<<dim3(BH, NN / 64), 256>>>(qp, ctx, den, ain);

    gemm_tf32<0><<<gD, 256>>>(ain, Wo, bo, attn, BN, DM, DM);
    add_ln<<<BN, 256>>>(video, attn, g2, be2, x);
    gemm_tf32<1><<<dim3(DFF / 128, BN / 128), 256>>>(x, W1, b1, h1, BN, DFF, DM);
    gemm_tf32<0><<<gD, 256>>>(h1, W2, b2, ff, BN, DM, DFF);
    add_ln<<<BN, 256>>>(x, ff, g3, be3, out);
}